// round 1
// baseline (speedup 1.0000x reference)
#include <cuda_runtime.h>
#include <cstdint>

#define NMAX 100000
#define MMAX 8192
#define KINF 0xFFFFFFFFFFFFFFFFULL
#define MAXB 1024

// ---------------- static device scratch (no allocations allowed) -------------
__device__ unsigned long long g_key[NMAX];
__device__ unsigned long long g_minCur[NMAX];
__device__ unsigned long long g_minNew[NMAX];
__device__ unsigned char g_mask[NMAX];
__device__ unsigned char g_maskP[NMAX];
__device__ unsigned char g_mis[NMAX];
__device__ int g_misIdx[NMAX];
__device__ int g_cluster[NMAX];
__device__ float g_dense[(size_t)MMAX * (size_t)MMAX];      // 256 MB
__device__ unsigned char g_flagA[(size_t)MMAX * (size_t)MMAX]; // 64 MB
__device__ int g_nodeCnt[MAXB];
__device__ int g_nodeOff[MAXB];
__device__ int g_cellCnt[MAXB];
__device__ int g_cellOff[MAXB];
__device__ int g_cnt2[2];
__device__ unsigned long long g_maxMisKey;
__device__ int g_M;
__device__ int g_P;
__device__ unsigned int g_arrive;

// ---------------- helpers ----------------------------------------------------

// Monotonic-counter grid barrier (all blocks co-resident by construction).
__device__ __forceinline__ void grid_bar(unsigned nb, unsigned &target) {
    __threadfence();              // release: my writes visible before arrival
    __syncthreads();
    if (threadIdx.x == 0) {
        target += nb;
        atomicAdd(&g_arrive, 1u);
        while (*((volatile unsigned*)&g_arrive) < target) __nanosleep(64);
        __threadfence();          // acquire
    }
    __syncthreads();
}

__device__ __forceinline__ int block_reduce_add(int v) {
    __shared__ int shr[32];
    int lane = threadIdx.x & 31;
    int w = threadIdx.x >> 5;
    #pragma unroll
    for (int o = 16; o; o >>= 1) v += __shfl_down_sync(0xffffffffu, v, o);
    if (lane == 0) shr[w] = v;
    __syncthreads();
    int nw = (blockDim.x + 31) >> 5;
    int r = 0;
    if (w == 0) {
        r = (lane < nw) ? shr[lane] : 0;
        #pragma unroll
        for (int o = 16; o; o >>= 1) r += __shfl_down_sync(0xffffffffu, r, o);
    }
    __syncthreads();
    return r;  // valid on threadIdx.x == 0
}

// Exclusive block scan (Hillis-Steele); all threads must participate.
__device__ __forceinline__ int block_excl_scan(int v, int &total) {
    __shared__ int sh[1024];
    int t = threadIdx.x;
    sh[t] = v;
    __syncthreads();
    for (int off = 1; off < blockDim.x; off <<= 1) {
        int y = (t >= off) ? sh[t - off] : 0;
        __syncthreads();
        sh[t] += y;
        __syncthreads();
    }
    int incl = sh[t];
    total = sh[blockDim.x - 1];
    __syncthreads();
    return incl - v;
}

// ---------------- kernels -----------------------------------------------------

__global__ void k_init(const float* __restrict__ score, int n) {
    int v = blockIdx.x * blockDim.x + threadIdx.x;
    if (v < n) {
        unsigned long long k =
            ((unsigned long long)__float_as_uint(score[v]) << 32) | (unsigned)v;
        g_key[v] = k; g_minCur[v] = k; g_minNew[v] = k;
        g_mask[v] = 0; g_maskP[v] = 0; g_mis[v] = 0;
    }
    if (v == 0) {
        g_arrive = 0;
        g_cnt2[0] = 0; g_cnt2[1] = 1;   // slot 1 read at top of round 0
        g_maxMisKey = 0; g_M = 0; g_P = 0;
    }
}

// Persistent kernel: full MIS loop + clustering, device-side convergence.
__global__ void __launch_bounds__(256, 4)
k_persist(const int* __restrict__ erow, const int* __restrict__ ecol,
          int n, int e, const float* __restrict__ x, int d,
          float* __restrict__ out)
{
    const unsigned nb = gridDim.x;
    const unsigned nt = nb * blockDim.x;
    const unsigned tid = blockIdx.x * blockDim.x + threadIdx.x;
    unsigned bt = 0;

    // ---------------- MIS loop (exact 1-hop semantics via double buffering) --
    for (int round = 0; round < 100000; ++round) {
        if (*((volatile int*)&g_cnt2[(round + 1) & 1]) == 0) break;

        // A: min-key propagation (minCur read-only, minNew accum)
        for (unsigned i = tid; i < (unsigned)e; i += nt) {
            unsigned long long mv = g_minCur[erow[i]];
            if (mv != KINF) atomicMin(&g_minNew[ecol[i]], mv);
        }
        grid_bar(nb, bt);

        // B: local minima join MIS
        if (tid == 0) g_cnt2[(round + 1) & 1] = 0;  // recycle counter slot
        for (unsigned v = tid; v < (unsigned)n; v += nt) {
            unsigned char m = g_mask[v];
            if (!m && g_key[v] == g_minNew[v]) { g_mis[v] = 1; g_mask[v] = 1; m = 1; }
            g_maskP[v] = m;
        }
        grid_bar(nb, bt);

        // C: mask dilation by exactly 1 hop (read mask, write maskP)
        for (unsigned i = tid; i < (unsigned)e; i += nt) {
            if (g_mask[erow[i]]) g_maskP[ecol[i]] = 1;
        }
        grid_bar(nb, bt);

        // D: commit mask, reset min arrays, count unmasked
        int local = 0;
        for (unsigned v = tid; v < (unsigned)n; v += nt) {
            unsigned char m = g_maskP[v];
            g_mask[v] = m;
            unsigned long long val = m ? KINF : g_key[v];
            g_minCur[v] = val; g_minNew[v] = val;
            local += (m == 0);
        }
        int bs = block_reduce_add(local);
        if (threadIdx.x == 0 && bs) atomicAdd(&g_cnt2[round & 1], bs);
        grid_bar(nb, bt);
    }

    // ---------------- clustering ---------------------------------------------
    // E: seed min arrays with MIS keys; track max MIS key (fallback cluster)
    for (unsigned v = tid; v < (unsigned)n; v += nt) {
        unsigned long long mc;
        if (g_mis[v]) { mc = g_key[v]; atomicMax(&g_maxMisKey, mc); }
        else mc = KINF;
        g_minCur[v] = mc; g_minNew[v] = mc;
    }
    // per-block MIS counts on contiguous chunks (for stable prefix sum)
    int chunk = (n + (int)nb - 1) / (int)nb;
    int cs = (int)blockIdx.x * chunk;
    int ce = cs + chunk; if (ce > n) ce = n;
    {
        int cnt = 0;
        for (int v = cs + (int)threadIdx.x; v < ce; v += (int)blockDim.x)
            cnt += g_mis[v];
        int bs = block_reduce_add(cnt);
        if (threadIdx.x == 0) g_nodeCnt[blockIdx.x] = bs;
    }
    grid_bar(nb, bt);

    // F: scan of block counts (tiny)
    if (blockIdx.x == 0 && threadIdx.x == 0) {
        int s = 0;
        for (unsigned i = 0; i < nb; ++i) { int c = g_nodeCnt[i]; g_nodeOff[i] = s; s += c; }
        if (s > MMAX) s = MMAX;   // safety clamp (never expected)
        g_M = s;
    }
    grid_bar(nb, bt);

    // G: misIdx = exclusive prefix of mis flags (tile loop; chunk may exceed blockDim)
    {
        int run = g_nodeOff[blockIdx.x];
        for (int t0 = cs; t0 < ce; t0 += (int)blockDim.x) {
            int v = t0 + (int)threadIdx.x;
            int f = (v < ce) ? (int)g_mis[v] : 0;
            int tot;
            int ex = block_excl_scan(f, tot);
            if (v < ce) g_misIdx[v] = run + ex;
            run += tot;
        }
    }
    grid_bar(nb, bt);

    // H: one min-key propagation (k = 1)
    for (unsigned i = tid; i < (unsigned)e; i += nt) {
        unsigned long long mv = g_minCur[erow[i]];
        if (mv != KINF) atomicMin(&g_minNew[ecol[i]], mv);
    }
    grid_bar(nb, bt);

    // I: cluster assignment (low 32 bits of winning key = MIS node index)
    int fb = g_misIdx[(unsigned)(g_maxMisKey & 0xffffffffULL)];  // jnp clip behavior
    for (unsigned v = tid; v < (unsigned)n; v += nt) {
        unsigned long long mk = g_minNew[v];
        g_cluster[v] = (mk == KINF) ? fb : g_misIdx[(unsigned)(mk & 0xffffffffULL)];
    }

    // J: x_out = x[mis] (node-index order), rows of d floats
    int dv = d >> 2;
    for (unsigned v = tid; v < (unsigned)n; v += nt) {
        if (g_mis[v]) {
            const float4* src = (const float4*)(x + (size_t)v * d);
            float4* dst = (float4*)(out + (size_t)g_misIdx[v] * d);
            for (int j = 0; j < dv; ++j) dst[j] = src[j];
        }
    }
}

__global__ void k_zero() {
    size_t MM = (size_t)g_M * (size_t)g_M;
    size_t nt = (size_t)gridDim.x * blockDim.x;
    for (size_t i = (size_t)blockIdx.x * blockDim.x + threadIdx.x; i < MM; i += nt) {
        g_dense[i] = 0.0f;
        g_flagA[i] = 0;
    }
}

__global__ void k_accum(const int* __restrict__ erow, const int* __restrict__ ecol,
                        const float* __restrict__ attr, int e) {
    unsigned M = (unsigned)g_M;
    unsigned nt = gridDim.x * blockDim.x;
    for (unsigned i = blockIdx.x * blockDim.x + threadIdx.x; i < (unsigned)e; i += nt) {
        unsigned idx = (unsigned)g_cluster[erow[i]] * M + (unsigned)g_cluster[ecol[i]];
        atomicAdd(&g_dense[idx], attr[i]);
        g_flagA[idx] = 1;
    }
}

__global__ void k_count() {
    unsigned M = (unsigned)g_M;
    size_t MM = (size_t)M * M;
    size_t chunk = (MM + gridDim.x - 1) / gridDim.x;
    size_t s = (size_t)blockIdx.x * chunk;
    size_t epos = s + chunk; if (epos > MM) epos = MM;
    int cnt = 0;
    for (size_t i = s + threadIdx.x; i < epos; i += blockDim.x) {
        if (g_flagA[i]) {
            unsigned ii = (unsigned)i;
            unsigned r = ii / M, c = ii - r * M;
            cnt += (r != c);
        }
    }
    int bs = block_reduce_add(cnt);
    if (threadIdx.x == 0) g_cellCnt[blockIdx.x] = bs;
}

__global__ void k_scan(int nb2) {
    int t = threadIdx.x;
    int v = (t < nb2) ? g_cellCnt[t] : 0;
    int tot;
    int ex = block_excl_scan(v, tot);
    if (t < nb2) g_cellOff[t] = ex;
    if (t == 0) g_P = tot;
}

__global__ void k_write(float* __restrict__ out, int d) {
    unsigned M = (unsigned)g_M;
    size_t MM = (size_t)M * M;
    size_t P = (size_t)g_P;
    size_t xoff = (size_t)M * (size_t)d;
    size_t chunk = (MM + gridDim.x - 1) / gridDim.x;
    size_t s = (size_t)blockIdx.x * chunk;
    size_t epos = s + chunk; if (epos > MM) epos = MM;
    size_t base = (size_t)g_cellOff[blockIdx.x];
    for (size_t t0 = s; t0 < epos; t0 += blockDim.x) {
        size_t i = t0 + threadIdx.x;
        int keep = 0; unsigned r = 0, c = 0; float val = 0.f;
        if (i < epos && g_flagA[i]) {
            unsigned ii = (unsigned)i;
            r = ii / M; c = ii - r * M;
            if (r != c) { keep = 1; val = g_dense[i]; }
        }
        int tot;
        int ex = block_excl_scan(keep, tot);
        if (keep) {
            size_t p = base + (size_t)ex;
            out[xoff + p] = (float)r;           // edge_index_out row
            out[xoff + P + p] = (float)c;       // edge_index_out col
            out[xoff + 2 * P + p] = val;        // edge_attr_out
        }
        base += tot;
    }
}

__global__ void k_tail(float* __restrict__ out, const float* __restrict__ score,
                       int n, int d) {
    int v = blockIdx.x * blockDim.x + threadIdx.x;
    if (v >= n) return;
    size_t off = (size_t)g_M * (size_t)d + 3 * (size_t)g_P;
    out[off + v] = (float)g_cluster[v];
    out[off + (size_t)n + v] = g_mis[v] ? 1.0f : 0.0f;
    out[off + 2 * (size_t)n + v] = score[v];
}

// ---------------- entry -------------------------------------------------------
extern "C" void kernel_launch(void* const* d_in, const int* in_sizes, int n_in,
                              void* d_out, int out_size) {
    const float* x = (const float*)d_in[0];
    const int* ei = (const int*)d_in[1];
    const float* attr = (const float*)d_in[2];
    const float* score = (const float*)d_in[3];
    int n = in_sizes[3];
    int e = in_sizes[1] / 2;
    int d = in_sizes[0] / n;
    const int* erow = ei;
    const int* ecol = ei + e;
    float* out = (float*)d_out;

    int dev = 0;
    cudaGetDevice(&dev);
    int sms = 148;
    cudaDeviceGetAttribute(&sms, cudaDevAttrMultiProcessorCount, dev);
    int nb = sms * 4;
    if (nb > MAXB) nb = MAXB;

    k_init<<<(n + 255) / 256, 256>>>(score, n);
    k_persist<<<nb, 256>>>(erow, ecol, n, e, x, d, out);
    k_zero<<<2048, 256>>>();
    k_accum<<<4096, 256>>>(erow, ecol, attr, e);
    k_count<<<MAXB, 256>>>();
    k_scan<<<1, 1024>>>(MAXB);
    k_write<<<MAXB, 256>>>(out, d);
    k_tail<<<(n + 255) / 256, 256>>>(out, score, n, d);
}